// round 11
// baseline (speedup 1.0000x reference)
#include <cuda_runtime.h>
#include <stdint.h>

#define D 64
#define N_MAX 100096
#define SLOT_STRIDE 64
#define SA_STRIDE 72
#define TILE_ROWS 96
#define M_ITERS 6
#define NPW 16               // nodes per warp in k_spmm

// ---------------- scratch ----------------
__device__ __align__(16) float g_z[(size_t)N_MAX * D];   // Z = X @ W^T
__device__ int   g_cnt[N_MAX];
__device__ int   g_slot[(size_t)N_MAX * SLOT_STRIDE];
__device__ __align__(16) float g_wt[D * D];              // g_wt[k*64+j] = W[j][k]
__device__ __align__(16) float g_sum[D];
__device__ __align__(16) float g_sq[D];
__device__ int   g_is64;

__device__ __forceinline__ int edge_idx(const void* ei, int half, int E, int e, int is64) {
    if (is64) return (int)((const long long*)ei)[(size_t)half * E + e];
    return ((const int*)ei)[(size_t)half * E + e];
}

// ---------------- K0: zero + dtype detect + W transpose ----------------
__global__ void k_zero(const unsigned int* __restrict__ w,
                       const float* __restrict__ W, int n) {
    int i = blockIdx.x * blockDim.x + threadIdx.x;
    if (i < n) g_cnt[i] = 0;
    if (i < D) { g_sum[i] = 0.f; g_sq[i] = 0.f; }
    if (i < D * D) {
        int k = i >> 6, j = i & 63;
        g_wt[i] = W[j * D + k];
    }
    if (blockIdx.x == 0 && threadIdx.x == 0) {
        int all0 = 1;
        #pragma unroll
        for (int kk = 0; kk < 32; kk++)
            if (w[2 * kk + 1] != 0u) { all0 = 0; break; }
        g_is64 = all0;
    }
}

// ---------------- K1: build padded adjacency ----------------
__global__ void k_build(const void* __restrict__ ei, int E, int n) {
    int e = blockIdx.x * blockDim.x + threadIdx.x;
    if (e >= E) return;
    int is64 = g_is64;
    int r  = edge_idx(ei, 0, E, e, is64);
    int cc = edge_idx(ei, 1, E, e, is64);
    if ((unsigned)r >= (unsigned)n || (unsigned)cc >= (unsigned)n) return;
    int pos = atomicAdd(&g_cnt[r], 1);
    if (pos < SLOT_STRIDE) g_slot[(size_t)r * SLOT_STRIDE + pos] = cc;
}

// ---------------- K2: Z = X @ W^T (96-row tile, f32x2 mainloop) ----------------
__global__ void __launch_bounds__(256)
k_gemm(const float* __restrict__ x, int n) {
    __shared__ float sw[D * D];
    __shared__ float sa[TILE_ROWS * SA_STRIDE];

    int t  = threadIdx.x;
    int r0 = blockIdx.x * TILE_ROWS;

    #pragma unroll
    for (int i = t; i < D * D / 4; i += 256)
        ((float4*)sw)[i] = ((const float4*)g_wt)[i];

    #pragma unroll
    for (int i = t; i < TILE_ROWS * 16; i += 256) {
        int r = i >> 4, c = i & 15;
        float4 v;
        if (r0 + r < n) v = ((const float4*)x)[(size_t)(r0 + r) * 16 + c];
        else            v = make_float4(0.f, 0.f, 0.f, 0.f);
        *(float4*)&sa[r * SA_STRIDE + c * 4] = v;
    }
    __syncthreads();

    int tj = t & 15;
    int ti = t >> 4;

    unsigned long long acc01[M_ITERS], acc23[M_ITERS];
    #pragma unroll
    for (int m = 0; m < M_ITERS; m++) { acc01[m] = 0ull; acc23[m] = 0ull; }

    #pragma unroll
    for (int k = 0; k < D; k += 4) {
        unsigned long long w01[4], w23[4];
        #pragma unroll
        for (int kk = 0; kk < 4; kk++) {
            const unsigned long long* wp =
                (const unsigned long long*)&sw[(k + kk) * D + tj * 4];
            w01[kk] = wp[0];
            w23[kk] = wp[1];
        }
        #pragma unroll
        for (int m = 0; m < M_ITERS; m++) {
            float4 a = *(const float4*)&sa[(ti + 16 * m) * SA_STRIDE + k];
            unsigned long long aa;
            asm("mov.b64 %0, {%1, %1};" : "=l"(aa) : "r"(__float_as_uint(a.x)));
            asm("fma.rn.f32x2 %0, %1, %2, %0;" : "+l"(acc01[m]) : "l"(aa), "l"(w01[0]));
            asm("fma.rn.f32x2 %0, %1, %2, %0;" : "+l"(acc23[m]) : "l"(aa), "l"(w23[0]));
            asm("mov.b64 %0, {%1, %1};" : "=l"(aa) : "r"(__float_as_uint(a.y)));
            asm("fma.rn.f32x2 %0, %1, %2, %0;" : "+l"(acc01[m]) : "l"(aa), "l"(w01[1]));
            asm("fma.rn.f32x2 %0, %1, %2, %0;" : "+l"(acc23[m]) : "l"(aa), "l"(w23[1]));
            asm("mov.b64 %0, {%1, %1};" : "=l"(aa) : "r"(__float_as_uint(a.z)));
            asm("fma.rn.f32x2 %0, %1, %2, %0;" : "+l"(acc01[m]) : "l"(aa), "l"(w01[2]));
            asm("fma.rn.f32x2 %0, %1, %2, %0;" : "+l"(acc23[m]) : "l"(aa), "l"(w23[2]));
            asm("mov.b64 %0, {%1, %1};" : "=l"(aa) : "r"(__float_as_uint(a.w)));
            asm("fma.rn.f32x2 %0, %1, %2, %0;" : "+l"(acc01[m]) : "l"(aa), "l"(w01[3]));
            asm("fma.rn.f32x2 %0, %1, %2, %0;" : "+l"(acc23[m]) : "l"(aa), "l"(w23[3]));
        }
    }

    #pragma unroll
    for (int m = 0; m < M_ITERS; m++) {
        int row = r0 + ti + 16 * m;
        if (row < n) {
            unsigned int l0, h0, l1, h1;
            asm("mov.b64 {%0, %1}, %2;" : "=r"(l0), "=r"(h0) : "l"(acc01[m]));
            asm("mov.b64 {%0, %1}, %2;" : "=r"(l1), "=r"(h1) : "l"(acc23[m]));
            float4 z;
            z.x = __uint_as_float(l0);
            z.y = __uint_as_float(h0);
            z.z = __uint_as_float(l1);
            z.w = __uint_as_float(h1);
            *(float4*)(g_z + (size_t)row * D + tj * 4) = z;
        }
    }
}

// ---------------- K3: out = relu(S @ Z + b), fused BN partials ----------------
// Warp per node, 16 nodes per warp; block = 8 warps = 128 nodes.
__global__ void __launch_bounds__(256)
k_spmm(const float* __restrict__ bias, float* __restrict__ out, int n) {
    __shared__ float2 ssum[8][32];
    __shared__ float2 ssq[8][32];

    int wid  = threadIdx.x >> 5;
    int lane = threadIdx.x & 31;
    int base = (blockIdx.x * 8 + wid) * NPW;

    float2 b2 = ((const float2*)bias)[lane];
    const float2* zb = (const float2*)g_z;

    float csx = 0.f, csy = 0.f, cqx = 0.f, cqy = 0.f;

    #pragma unroll 1
    for (int it = 0; it < NPW; it++) {
        int node = base + it;
        if (node >= n) break;
        int deg = g_cnt[node];
        if (deg > SLOT_STRIDE) deg = SLOT_STRIDE;
        float di = rsqrtf(1.0f + (float)deg);

        size_t loff = (size_t)node * 32 + lane;
        float2 zv = __ldg(zb + loff);
        float ax = di * zv.x, ay = di * zv.y;

        const int* slots = g_slot + (size_t)node * SLOT_STRIDE;
        int k = 0;
        for (; k + 8 <= deg; k += 8) {
            int c[8];
            #pragma unroll
            for (int j = 0; j < 8; j++) c[j] = slots[k + j];
            float d[8];
            #pragma unroll
            for (int j = 0; j < 8; j++) d[j] = rsqrtf(1.0f + (float)g_cnt[c[j]]);
            float2 v[8];
            #pragma unroll
            for (int j = 0; j < 8; j++) v[j] = __ldg(zb + (size_t)c[j] * 32 + lane);
            #pragma unroll
            for (int j = 0; j < 8; j++) { ax += d[j] * v[j].x; ay += d[j] * v[j].y; }
        }
        for (; k < deg; k++) {
            int cc = slots[k];
            float dc = rsqrtf(1.0f + (float)g_cnt[cc]);
            float2 v = __ldg(zb + (size_t)cc * 32 + lane);
            ax += dc * v.x; ay += dc * v.y;
        }

        float yx = fmaxf(ax * di + b2.x, 0.f);
        float yy = fmaxf(ay * di + b2.y, 0.f);
        ((float2*)out)[loff] = make_float2(yx, yy);
        csx += yx; cqx += yx * yx;
        csy += yy; cqy += yy * yy;
    }

    ssum[wid][lane] = make_float2(csx, csy);
    ssq[wid][lane]  = make_float2(cqx, cqy);
    __syncthreads();

    if (threadIdx.x < 32) {
        float sx = 0.f, sy = 0.f, qx = 0.f, qy = 0.f;
        #pragma unroll
        for (int g = 0; g < 8; g++) {
            float2 p = ssum[g][threadIdx.x];
            float2 q = ssq[g][threadIdx.x];
            sx += p.x; sy += p.y; qx += q.x; qy += q.y;
        }
        atomicAdd(&g_sum[2 * threadIdx.x],     sx);
        atomicAdd(&g_sum[2 * threadIdx.x + 1], sy);
        atomicAdd(&g_sq[2 * threadIdx.x],      qx);
        atomicAdd(&g_sq[2 * threadIdx.x + 1],  qy);
    }
}

// ---------------- K4: normalize (stats inline) ----------------
__global__ void k_norm(float* __restrict__ out,
                       const float* __restrict__ gamma,
                       const float* __restrict__ beta,
                       float invN, int n) {
    int t = blockIdx.x * blockDim.x + threadIdx.x;
    if (t >= n * 16) return;
    int c = t & 15;
    float4 s4 = ((const float4*)g_sum)[c];
    float4 q4 = ((const float4*)g_sq)[c];
    float4 gm = ((const float4*)gamma)[c];
    float4 bt = ((const float4*)beta)[c];
    float4 sc, sh;
    {
        float m = s4.x * invN, vv = q4.x * invN - m * m;
        sc.x = gm.x * rsqrtf(vv + 1e-5f); sh.x = bt.x - m * sc.x;
        m = s4.y * invN; vv = q4.y * invN - m * m;
        sc.y = gm.y * rsqrtf(vv + 1e-5f); sh.y = bt.y - m * sc.y;
        m = s4.z * invN; vv = q4.z * invN - m * m;
        sc.z = gm.z * rsqrtf(vv + 1e-5f); sh.z = bt.z - m * sc.z;
        m = s4.w * invN; vv = q4.w * invN - m * m;
        sc.w = gm.w * rsqrtf(vv + 1e-5f); sh.w = bt.w - m * sc.w;
    }
    float4 v = ((float4*)out)[t];
    v.x = v.x * sc.x + sh.x;
    v.y = v.y * sc.y + sh.y;
    v.z = v.z * sc.z + sh.z;
    v.w = v.w * sc.w + sh.w;
    ((float4*)out)[t] = v;
}

// ---------------- launch ----------------
extern "C" void kernel_launch(void* const* d_in, const int* in_sizes, int n_in,
                              void* d_out, int out_size) {
    const float* x     = (const float*)d_in[0];
    const void*  ei    = d_in[1];
    const float* W     = (const float*)d_in[2];
    const float* bias  = (const float*)d_in[3];
    const float* gamma = (const float*)d_in[4];
    const float* beta  = (const float*)d_in[5];
    float*       out   = (float*)d_out;

    int n = in_sizes[0] / D;
    int E = in_sizes[1] / 2;

    k_zero <<<(n + 255) / 256, 256>>>((const unsigned int*)ei, W, n);
    k_build<<<(E + 255) / 256, 256>>>(ei, E, n);
    k_gemm <<<(n + TILE_ROWS - 1) / TILE_ROWS, 256>>>(x, n);
    k_spmm <<<(n + 8 * NPW - 1) / (8 * NPW), 256>>>(bias, out, n);
    k_norm <<<(n * 16 + 255) / 256, 256>>>(out, gamma, beta, 1.0f / (float)n, n);
}

// round 12
// speedup vs baseline: 1.1680x; 1.1680x over previous
#include <cuda_runtime.h>
#include <stdint.h>

#define D 64
#define N_MAX 100096
#define SLOT_STRIDE 64
#define SA_STRIDE 72
#define TILE_ROWS 96
#define M_ITERS 6

// ---------------- scratch ----------------
__device__ __align__(16) float g_agg[(size_t)N_MAX * D];
__device__ int   g_cnt[N_MAX];
__device__ int   g_slot[(size_t)N_MAX * SLOT_STRIDE];
__device__ __align__(16) float g_wt[D * D];      // g_wt[k*64+j] = W[j][k]
__device__ __align__(16) float g_sum[D];
__device__ __align__(16) float g_sq[D];
__device__ int   g_is64;

__device__ __forceinline__ int edge_idx(const void* ei, int half, int E, int e, int is64) {
    if (is64) return (int)((const long long*)ei)[(size_t)half * E + e];
    return ((const int*)ei)[(size_t)half * E + e];
}

// ---------------- K0: zero + dtype detect + W transpose ----------------
__global__ void k_zero(const unsigned int* __restrict__ w,
                       const float* __restrict__ W, int n) {
    int i = blockIdx.x * blockDim.x + threadIdx.x;
    if (i < n) g_cnt[i] = 0;
    if (i < D) { g_sum[i] = 0.f; g_sq[i] = 0.f; }
    if (i < D * D) {
        int k = i >> 6, j = i & 63;
        g_wt[i] = W[j * D + k];
    }
    if (blockIdx.x == 0 && threadIdx.x == 0) {
        int all0 = 1;
        #pragma unroll
        for (int kk = 0; kk < 32; kk++)
            if (w[2 * kk + 1] != 0u) { all0 = 0; break; }
        g_is64 = all0;
    }
}

// ---------------- K1: build padded adjacency ----------------
__global__ void k_build(const void* __restrict__ ei, int E, int n) {
    int e = blockIdx.x * blockDim.x + threadIdx.x;
    if (e >= E) return;
    int is64 = g_is64;
    int r  = edge_idx(ei, 0, E, e, is64);
    int cc = edge_idx(ei, 1, E, e, is64);
    if ((unsigned)r >= (unsigned)n || (unsigned)cc >= (unsigned)n) return;
    int pos = atomicAdd(&g_cnt[r], 1);
    if (pos < SLOT_STRIDE) g_slot[(size_t)r * SLOT_STRIDE + pos] = cc;
}

// ---------------- K2: pull-mode SpMM, warp-per-node, shfl-distributed meta ----
__global__ void __launch_bounds__(256)
k_spmm(const float* __restrict__ x, int n) {
    int warp = (blockIdx.x * blockDim.x + threadIdx.x) >> 5;
    int lane = threadIdx.x & 31;
    if (warp >= n) return;
    int node = warp;
    int deg  = g_cnt[node];
    if (deg > SLOT_STRIDE) deg = SLOT_STRIDE;
    float di = rsqrtf(1.0f + (float)deg);
    const float2* xb = (const float2*)x;
    size_t loff = (size_t)node * 32 + lane;

    float2 xv = __ldg(xb + loff);
    float ax = di * xv.x, ay = di * xv.y;

    const int* slots = g_slot + (size_t)node * SLOT_STRIDE;

    for (int base = 0; base < deg; base += 32) {
        int m = deg - base;
        if (m > 32) m = 32;
        // one coalesced load of up to 32 neighbor ids + their degree-norms
        int   myc  = 0;
        float mydc = 0.f;
        if (lane < m) {
            myc  = slots[base + lane];
            mydc = rsqrtf(1.0f + (float)g_cnt[myc]);
        }
        int j = 0;
        for (; j + 4 <= m; j += 4) {
            int   c0 = __shfl_sync(~0u, myc,  j    );
            int   c1 = __shfl_sync(~0u, myc,  j + 1);
            int   c2 = __shfl_sync(~0u, myc,  j + 2);
            int   c3 = __shfl_sync(~0u, myc,  j + 3);
            float d0 = __shfl_sync(~0u, mydc, j    );
            float d1 = __shfl_sync(~0u, mydc, j + 1);
            float d2 = __shfl_sync(~0u, mydc, j + 2);
            float d3 = __shfl_sync(~0u, mydc, j + 3);
            float2 v0 = __ldg(xb + (size_t)c0 * 32 + lane);
            float2 v1 = __ldg(xb + (size_t)c1 * 32 + lane);
            float2 v2 = __ldg(xb + (size_t)c2 * 32 + lane);
            float2 v3 = __ldg(xb + (size_t)c3 * 32 + lane);
            ax += d0 * v0.x; ay += d0 * v0.y;
            ax += d1 * v1.x; ay += d1 * v1.y;
            ax += d2 * v2.x; ay += d2 * v2.y;
            ax += d3 * v3.x; ay += d3 * v3.y;
        }
        for (; j < m; j++) {
            int   cc = __shfl_sync(~0u, myc,  j);
            float dc = __shfl_sync(~0u, mydc, j);
            float2 v = __ldg(xb + (size_t)cc * 32 + lane);
            ax += dc * v.x; ay += dc * v.y;
        }
    }
    ((float2*)g_agg)[loff] = make_float2(ax * di, ay * di);
}

// ---------------- K3: y = relu(agg @ W^T + b) + BN partials (f32x2) ----------
__global__ void __launch_bounds__(256)
k_gemm(const float* __restrict__ bias, float* __restrict__ out, int n) {
    __shared__ float  sw[D * D];
    __shared__ float  sa[TILE_ROWS * SA_STRIDE];
    __shared__ float2 swarp[8][D];

    int t  = threadIdx.x;
    int r0 = blockIdx.x * TILE_ROWS;

    #pragma unroll
    for (int i = t; i < D * D / 4; i += 256)
        ((float4*)sw)[i] = ((const float4*)g_wt)[i];

    #pragma unroll
    for (int i = t; i < TILE_ROWS * 16; i += 256) {
        int r = i >> 4, c = i & 15;
        float4 v;
        if (r0 + r < n) v = ((const float4*)g_agg)[(size_t)(r0 + r) * 16 + c];
        else            v = make_float4(0.f, 0.f, 0.f, 0.f);
        *(float4*)&sa[r * SA_STRIDE + c * 4] = v;
    }
    __syncthreads();

    int tj = t & 15;
    int ti = t >> 4;

    unsigned long long acc01[M_ITERS], acc23[M_ITERS];
    #pragma unroll
    for (int m = 0; m < M_ITERS; m++) { acc01[m] = 0ull; acc23[m] = 0ull; }

    #pragma unroll
    for (int k = 0; k < D; k += 4) {
        unsigned long long w01[4], w23[4];
        #pragma unroll
        for (int kk = 0; kk < 4; kk++) {
            const unsigned long long* wp =
                (const unsigned long long*)&sw[(k + kk) * D + tj * 4];
            w01[kk] = wp[0];
            w23[kk] = wp[1];
        }
        #pragma unroll
        for (int m = 0; m < M_ITERS; m++) {
            float4 a = *(const float4*)&sa[(ti + 16 * m) * SA_STRIDE + k];
            unsigned long long aa;
            asm("mov.b64 %0, {%1, %1};" : "=l"(aa) : "r"(__float_as_uint(a.x)));
            asm("fma.rn.f32x2 %0, %1, %2, %0;" : "+l"(acc01[m]) : "l"(aa), "l"(w01[0]));
            asm("fma.rn.f32x2 %0, %1, %2, %0;" : "+l"(acc23[m]) : "l"(aa), "l"(w23[0]));
            asm("mov.b64 %0, {%1, %1};" : "=l"(aa) : "r"(__float_as_uint(a.y)));
            asm("fma.rn.f32x2 %0, %1, %2, %0;" : "+l"(acc01[m]) : "l"(aa), "l"(w01[1]));
            asm("fma.rn.f32x2 %0, %1, %2, %0;" : "+l"(acc23[m]) : "l"(aa), "l"(w23[1]));
            asm("mov.b64 %0, {%1, %1};" : "=l"(aa) : "r"(__float_as_uint(a.z)));
            asm("fma.rn.f32x2 %0, %1, %2, %0;" : "+l"(acc01[m]) : "l"(aa), "l"(w01[2]));
            asm("fma.rn.f32x2 %0, %1, %2, %0;" : "+l"(acc23[m]) : "l"(aa), "l"(w23[2]));
            asm("mov.b64 %0, {%1, %1};" : "=l"(aa) : "r"(__float_as_uint(a.w)));
            asm("fma.rn.f32x2 %0, %1, %2, %0;" : "+l"(acc01[m]) : "l"(aa), "l"(w01[3]));
            asm("fma.rn.f32x2 %0, %1, %2, %0;" : "+l"(acc23[m]) : "l"(aa), "l"(w23[3]));
        }
    }

    float4 b4 = *(const float4*)&bias[tj * 4];
    float csum[4] = {0.f, 0.f, 0.f, 0.f};
    float csq[4]  = {0.f, 0.f, 0.f, 0.f};

    #pragma unroll
    for (int m = 0; m < M_ITERS; m++) {
        int row = r0 + ti + 16 * m;
        if (row < n) {
            unsigned int l0, h0, l1, h1;
            asm("mov.b64 {%0, %1}, %2;" : "=r"(l0), "=r"(h0) : "l"(acc01[m]));
            asm("mov.b64 {%0, %1}, %2;" : "=r"(l1), "=r"(h1) : "l"(acc23[m]));
            float4 y;
            y.x = fmaxf(__uint_as_float(l0) + b4.x, 0.f);
            y.y = fmaxf(__uint_as_float(h0) + b4.y, 0.f);
            y.z = fmaxf(__uint_as_float(l1) + b4.z, 0.f);
            y.w = fmaxf(__uint_as_float(h1) + b4.w, 0.f);
            *(float4*)(out + (size_t)row * D + tj * 4) = y;
            csum[0] += y.x; csq[0] += y.x * y.x;
            csum[1] += y.y; csq[1] += y.y * y.y;
            csum[2] += y.z; csq[2] += y.z * y.z;
            csum[3] += y.w; csq[3] += y.w * y.w;
        }
    }

    #pragma unroll
    for (int q = 0; q < 4; q++) {
        csum[q] += __shfl_down_sync(~0u, csum[q], 16);
        csq[q]  += __shfl_down_sync(~0u, csq[q], 16);
    }
    int warp = t >> 5, lane = t & 31;
    if (lane < 16) {
        #pragma unroll
        for (int q = 0; q < 4; q++)
            swarp[warp][lane * 4 + q] = make_float2(csum[q], csq[q]);
    }
    __syncthreads();

    if (t < D) {
        float s = 0.f, s2 = 0.f;
        #pragma unroll
        for (int g = 0; g < 8; g++) {
            float2 p = swarp[g][t];
            s += p.x; s2 += p.y;
        }
        atomicAdd(&g_sum[t], s);
        atomicAdd(&g_sq[t], s2);
    }
}

// ---------------- K4: normalize (stats inline) ----------------
__global__ void k_norm(float* __restrict__ out,
                       const float* __restrict__ gamma,
                       const float* __restrict__ beta,
                       float invN, int n) {
    int t = blockIdx.x * blockDim.x + threadIdx.x;
    if (t >= n * 16) return;
    int c = t & 15;
    float4 s4 = ((const float4*)g_sum)[c];
    float4 q4 = ((const float4*)g_sq)[c];
    float4 gm = ((const float4*)gamma)[c];
    float4 bt = ((const float4*)beta)[c];
    float4 sc, sh;
    {
        float m = s4.x * invN, vv = q4.x * invN - m * m;
        sc.x = gm.x * rsqrtf(vv + 1e-5f); sh.x = bt.x - m * sc.x;
        m = s4.y * invN; vv = q4.y * invN - m * m;
        sc.y = gm.y * rsqrtf(vv + 1e-5f); sh.y = bt.y - m * sc.y;
        m = s4.z * invN; vv = q4.z * invN - m * m;
        sc.z = gm.z * rsqrtf(vv + 1e-5f); sh.z = bt.z - m * sc.z;
        m = s4.w * invN; vv = q4.w * invN - m * m;
        sc.w = gm.w * rsqrtf(vv + 1e-5f); sh.w = bt.w - m * sc.w;
    }
    float4 v = ((float4*)out)[t];
    v.x = v.x * sc.x + sh.x;
    v.y = v.y * sc.y + sh.y;
    v.z = v.z * sc.z + sh.z;
    v.w = v.w * sc.w + sh.w;
    ((float4*)out)[t] = v;
}

// ---------------- launch ----------------
extern "C" void kernel_launch(void* const* d_in, const int* in_sizes, int n_in,
                              void* d_out, int out_size) {
    const float* x     = (const float*)d_in[0];
    const void*  ei    = d_in[1];
    const float* W     = (const float*)d_in[2];
    const float* bias  = (const float*)d_in[3];
    const float* gamma = (const float*)d_in[4];
    const float* beta  = (const float*)d_in[5];
    float*       out   = (float*)d_out;

    int n = in_sizes[0] / D;
    int E = in_sizes[1] / 2;

    k_zero <<<(n + 255) / 256, 256>>>((const unsigned int*)ei, W, n);
    k_build<<<(E + 255) / 256, 256>>>(ei, E, n);
    k_spmm <<<(n * 32 + 255) / 256, 256>>>(x, n);
    k_gemm <<<(n + TILE_ROWS - 1) / TILE_ROWS, 256>>>(bias, out, n);
    k_norm <<<(n * 16 + 255) / 256, 256>>>(out, gamma, beta, 1.0f / (float)n, n);
}

// round 13
// speedup vs baseline: 1.2188x; 1.0435x over previous
#include <cuda_runtime.h>
#include <stdint.h>

#define D 64
#define N_MAX 100096
#define SLOT_STRIDE 64
#define SA_STRIDE 72
#define TILE_ROWS 96
#define M_ITERS 6

// ---------------- scratch ----------------
__device__ __align__(16) float g_agg[(size_t)N_MAX * D];
__device__ int   g_cnt[N_MAX];
__device__ int   g_slot[(size_t)N_MAX * SLOT_STRIDE];
__device__ __align__(16) float g_wt[D * D];      // g_wt[k*64+j] = W[j][k]
__device__ __align__(16) float g_sum[D];
__device__ __align__(16) float g_sq[D];
__device__ int   g_is64;

// ---------------- K0: zero + dtype detect + W transpose ----------------
__global__ void k_zero(const unsigned int* __restrict__ w,
                       const float* __restrict__ W, int n) {
    int i = blockIdx.x * blockDim.x + threadIdx.x;
    if (i < n) g_cnt[i] = 0;
    if (i < D) { g_sum[i] = 0.f; g_sq[i] = 0.f; }
    if (i < D * D) {
        int k = i >> 6, j = i & 63;
        g_wt[i] = W[j * D + k];
    }
    if (blockIdx.x == 0 && threadIdx.x == 0) {
        int all0 = 1;
        #pragma unroll
        for (int kk = 0; kk < 32; kk++)
            if (w[2 * kk + 1] != 0u) { all0 = 0; break; }
        g_is64 = all0;
    }
}

// ---------------- K1: build padded adjacency, 2 edges/thread ----------------
__global__ void k_build(const void* __restrict__ ei, int E, int n) {
    int e = (blockIdx.x * blockDim.x + threadIdx.x) * 2;
    if (e >= E) return;
    int is64 = g_is64;
    int r0, c0, r1 = -1, c1 = -1;
    bool has2 = (e + 1 < E);
    if (is64) {
        const long long* p = (const long long*)ei;
        longlong2 rr = *(const longlong2*)(p + e);
        longlong2 cc = *(const longlong2*)(p + (size_t)E + e);   // E even -> aligned
        r0 = (int)rr.x; c0 = (int)cc.x;
        if (has2) { r1 = (int)rr.y; c1 = (int)cc.y; }
    } else {
        const int* p = (const int*)ei;
        int2 rr = *(const int2*)(p + e);
        int2 cc = *(const int2*)(p + (size_t)E + e);
        r0 = rr.x; c0 = cc.x;
        if (has2) { r1 = rr.y; c1 = cc.y; }
    }
    if ((unsigned)r0 < (unsigned)n && (unsigned)c0 < (unsigned)n) {
        int pos = atomicAdd(&g_cnt[r0], 1);
        if (pos < SLOT_STRIDE) g_slot[(size_t)r0 * SLOT_STRIDE + pos] = c0;
    }
    if (has2 && (unsigned)r1 < (unsigned)n && (unsigned)c1 < (unsigned)n) {
        int pos = atomicAdd(&g_cnt[r1], 1);
        if (pos < SLOT_STRIDE) g_slot[(size_t)r1 * SLOT_STRIDE + pos] = c1;
    }
}

// ---------------- K2: pull-mode SpMM, warp-per-node, unroll 8 (R10) ----------
__global__ void __launch_bounds__(256)
k_spmm(const float* __restrict__ x, int n) {
    int warp = (blockIdx.x * blockDim.x + threadIdx.x) >> 5;
    int lane = threadIdx.x & 31;
    if (warp >= n) return;
    int node = warp;
    int deg  = g_cnt[node];
    if (deg > SLOT_STRIDE) deg = SLOT_STRIDE;
    float di = rsqrtf(1.0f + (float)deg);
    const float2* xb = (const float2*)x;
    size_t loff = (size_t)node * 32 + lane;

    float2 xv = __ldg(xb + loff);
    float ax = di * xv.x, ay = di * xv.y;

    const int* slots = g_slot + (size_t)node * SLOT_STRIDE;
    int k = 0;
    for (; k + 8 <= deg; k += 8) {
        int c[8];
        #pragma unroll
        for (int j = 0; j < 8; j++) c[j] = slots[k + j];
        float d[8];
        #pragma unroll
        for (int j = 0; j < 8; j++) d[j] = rsqrtf(1.0f + (float)g_cnt[c[j]]);
        float2 v[8];
        #pragma unroll
        for (int j = 0; j < 8; j++) v[j] = __ldg(xb + (size_t)c[j] * 32 + lane);
        #pragma unroll
        for (int j = 0; j < 8; j++) { ax += d[j] * v[j].x; ay += d[j] * v[j].y; }
    }
    for (; k < deg; k++) {
        int cc = slots[k];
        float dc = rsqrtf(1.0f + (float)g_cnt[cc]);
        float2 v = __ldg(xb + (size_t)cc * 32 + lane);
        ax += dc * v.x; ay += dc * v.y;
    }
    ((float2*)g_agg)[loff] = make_float2(ax * di, ay * di);
}

// ---------------- K3: y = relu(agg @ W^T + b) + BN partials (f32x2) ----------
__global__ void __launch_bounds__(256)
k_gemm(const float* __restrict__ bias, float* __restrict__ out, int n) {
    __shared__ float  sw[D * D];
    __shared__ float  sa[TILE_ROWS * SA_STRIDE];
    __shared__ float2 swarp[8][D];

    int t  = threadIdx.x;
    int r0 = blockIdx.x * TILE_ROWS;

    #pragma unroll
    for (int i = t; i < D * D / 4; i += 256)
        ((float4*)sw)[i] = ((const float4*)g_wt)[i];

    #pragma unroll
    for (int i = t; i < TILE_ROWS * 16; i += 256) {
        int r = i >> 4, c = i & 15;
        float4 v;
        if (r0 + r < n) v = ((const float4*)g_agg)[(size_t)(r0 + r) * 16 + c];
        else            v = make_float4(0.f, 0.f, 0.f, 0.f);
        *(float4*)&sa[r * SA_STRIDE + c * 4] = v;
    }
    __syncthreads();

    int tj = t & 15;
    int ti = t >> 4;

    unsigned long long acc01[M_ITERS], acc23[M_ITERS];
    #pragma unroll
    for (int m = 0; m < M_ITERS; m++) { acc01[m] = 0ull; acc23[m] = 0ull; }

    #pragma unroll
    for (int k = 0; k < D; k += 4) {
        unsigned long long w01[4], w23[4];
        #pragma unroll
        for (int kk = 0; kk < 4; kk++) {
            const unsigned long long* wp =
                (const unsigned long long*)&sw[(k + kk) * D + tj * 4];
            w01[kk] = wp[0];
            w23[kk] = wp[1];
        }
        #pragma unroll
        for (int m = 0; m < M_ITERS; m++) {
            float4 a = *(const float4*)&sa[(ti + 16 * m) * SA_STRIDE + k];
            unsigned long long aa;
            asm("mov.b64 %0, {%1, %1};" : "=l"(aa) : "r"(__float_as_uint(a.x)));
            asm("fma.rn.f32x2 %0, %1, %2, %0;" : "+l"(acc01[m]) : "l"(aa), "l"(w01[0]));
            asm("fma.rn.f32x2 %0, %1, %2, %0;" : "+l"(acc23[m]) : "l"(aa), "l"(w23[0]));
            asm("mov.b64 %0, {%1, %1};" : "=l"(aa) : "r"(__float_as_uint(a.y)));
            asm("fma.rn.f32x2 %0, %1, %2, %0;" : "+l"(acc01[m]) : "l"(aa), "l"(w01[1]));
            asm("fma.rn.f32x2 %0, %1, %2, %0;" : "+l"(acc23[m]) : "l"(aa), "l"(w23[1]));
            asm("mov.b64 %0, {%1, %1};" : "=l"(aa) : "r"(__float_as_uint(a.z)));
            asm("fma.rn.f32x2 %0, %1, %2, %0;" : "+l"(acc01[m]) : "l"(aa), "l"(w01[2]));
            asm("fma.rn.f32x2 %0, %1, %2, %0;" : "+l"(acc23[m]) : "l"(aa), "l"(w23[2]));
            asm("mov.b64 %0, {%1, %1};" : "=l"(aa) : "r"(__float_as_uint(a.w)));
            asm("fma.rn.f32x2 %0, %1, %2, %0;" : "+l"(acc01[m]) : "l"(aa), "l"(w01[3]));
            asm("fma.rn.f32x2 %0, %1, %2, %0;" : "+l"(acc23[m]) : "l"(aa), "l"(w23[3]));
        }
    }

    float4 b4 = *(const float4*)&bias[tj * 4];
    float csum[4] = {0.f, 0.f, 0.f, 0.f};
    float csq[4]  = {0.f, 0.f, 0.f, 0.f};

    #pragma unroll
    for (int m = 0; m < M_ITERS; m++) {
        int row = r0 + ti + 16 * m;
        if (row < n) {
            unsigned int l0, h0, l1, h1;
            asm("mov.b64 {%0, %1}, %2;" : "=r"(l0), "=r"(h0) : "l"(acc01[m]));
            asm("mov.b64 {%0, %1}, %2;" : "=r"(l1), "=r"(h1) : "l"(acc23[m]));
            float4 y;
            y.x = fmaxf(__uint_as_float(l0) + b4.x, 0.f);
            y.y = fmaxf(__uint_as_float(h0) + b4.y, 0.f);
            y.z = fmaxf(__uint_as_float(l1) + b4.z, 0.f);
            y.w = fmaxf(__uint_as_float(h1) + b4.w, 0.f);
            *(float4*)(out + (size_t)row * D + tj * 4) = y;
            csum[0] += y.x; csq[0] += y.x * y.x;
            csum[1] += y.y; csq[1] += y.y * y.y;
            csum[2] += y.z; csq[2] += y.z * y.z;
            csum[3] += y.w; csq[3] += y.w * y.w;
        }
    }

    #pragma unroll
    for (int q = 0; q < 4; q++) {
        csum[q] += __shfl_down_sync(~0u, csum[q], 16);
        csq[q]  += __shfl_down_sync(~0u, csq[q], 16);
    }
    int warp = t >> 5, lane = t & 31;
    if (lane < 16) {
        #pragma unroll
        for (int q = 0; q < 4; q++)
            swarp[warp][lane * 4 + q] = make_float2(csum[q], csq[q]);
    }
    __syncthreads();

    if (t < D) {
        float s = 0.f, s2 = 0.f;
        #pragma unroll
        for (int g = 0; g < 8; g++) {
            float2 p = swarp[g][t];
            s += p.x; s2 += p.y;
        }
        atomicAdd(&g_sum[t], s);
        atomicAdd(&g_sq[t], s2);
    }
}

// ---------------- K4: normalize (stats inline) ----------------
__global__ void k_norm(float* __restrict__ out,
                       const float* __restrict__ gamma,
                       const float* __restrict__ beta,
                       float invN, int n) {
    int t = blockIdx.x * blockDim.x + threadIdx.x;
    if (t >= n * 16) return;
    int c = t & 15;
    float4 s4 = ((const float4*)g_sum)[c];
    float4 q4 = ((const float4*)g_sq)[c];
    float4 gm = ((const float4*)gamma)[c];
    float4 bt = ((const float4*)beta)[c];
    float4 sc, sh;
    {
        float m = s4.x * invN, vv = q4.x * invN - m * m;
        sc.x = gm.x * rsqrtf(vv + 1e-5f); sh.x = bt.x - m * sc.x;
        m = s4.y * invN; vv = q4.y * invN - m * m;
        sc.y = gm.y * rsqrtf(vv + 1e-5f); sh.y = bt.y - m * sc.y;
        m = s4.z * invN; vv = q4.z * invN - m * m;
        sc.z = gm.z * rsqrtf(vv + 1e-5f); sh.z = bt.z - m * sc.z;
        m = s4.w * invN; vv = q4.w * invN - m * m;
        sc.w = gm.w * rsqrtf(vv + 1e-5f); sh.w = bt.w - m * sc.w;
    }
    float4 v = ((float4*)out)[t];
    v.x = v.x * sc.x + sh.x;
    v.y = v.y * sc.y + sh.y;
    v.z = v.z * sc.z + sh.z;
    v.w = v.w * sc.w + sh.w;
    ((float4*)out)[t] = v;
}

// ---------------- launch ----------------
extern "C" void kernel_launch(void* const* d_in, const int* in_sizes, int n_in,
                              void* d_out, int out_size) {
    const float* x     = (const float*)d_in[0];
    const void*  ei    = d_in[1];
    const float* W     = (const float*)d_in[2];
    const float* bias  = (const float*)d_in[3];
    const float* gamma = (const float*)d_in[4];
    const float* beta  = (const float*)d_in[5];
    float*       out   = (float*)d_out;

    int n = in_sizes[0] / D;
    int E = in_sizes[1] / 2;

    k_zero <<<(n + 255) / 256, 256>>>((const unsigned int*)ei, W, n);
    k_build<<<(E / 2 + 255) / 256, 256>>>(ei, E, n);
    k_spmm <<<(n * 32 + 255) / 256, 256>>>(x, n);
    k_gemm <<<(n + TILE_ROWS - 1) / TILE_ROWS, 256>>>(bias, out, n);
    k_norm <<<(n * 16 + 255) / 256, 256>>>(out, gamma, beta, 1.0f / (float)n, n);
}